// round 15
// baseline (speedup 1.0000x reference)
#include <cuda_runtime.h>
#include <math.h>
#include <stdint.h>

#define B_   2
#define S_   2048
#define H_   2048
#define NH_  16
#define NKV_ 4
#define HD_  128
#define LAT_ 256
#define TOK  (B_ * S_)

// ---------------- scratch (no allocations allowed) ----------------
__device__ float gQ[(size_t)TOK * H_];            // 32 MB
__device__ float gK[(size_t)TOK * NKV_ * HD_];    // 8 MB
__device__ float gV[(size_t)TOK * NKV_ * HD_];    // 8 MB
__device__ float gLat[(size_t)TOK * LAT_];        // 4 MB
__device__ float gCtx[(size_t)TOK * H_];          // 32 MB

// ---------------- tf32 helpers ----------------
__device__ __forceinline__ uint32_t f2tf(float x) {
    uint32_t r;
    asm("cvt.rna.tf32.f32 %0, %1;" : "=r"(r) : "f"(x));
    return r;
}

__device__ __forceinline__ void mma_tf32(float (&d)[4], const uint32_t (&a)[4],
                                         const uint32_t (&b)[2]) {
    asm volatile(
        "mma.sync.aligned.m16n8k8.row.col.f32.tf32.tf32.f32 "
        "{%0,%1,%2,%3}, {%4,%5,%6,%7}, {%8,%9}, {%0,%1,%2,%3};"
        : "+f"(d[0]), "+f"(d[1]), "+f"(d[2]), "+f"(d[3])
        : "r"(a[0]), "r"(a[1]), "r"(a[2]), "r"(a[3]), "r"(b[0]), "r"(b[1]));
}

__device__ __forceinline__ void ldsm4(uint32_t (&r)[4], uint32_t addr) {
    asm volatile("ldmatrix.sync.aligned.m8n8.x4.shared.b16 {%0,%1,%2,%3}, [%4];"
                 : "=r"(r[0]), "=r"(r[1]), "=r"(r[2]), "=r"(r[3]) : "r"(addr));
}

// =====================================================================
// GEMM core: acc += Ablk[128,K] @ Bblk[128,K]^T   (NT, tf32 tensor cores)
// Prefetch distance 2: register stages ping-pong by (kt & 1).
// =====================================================================
__device__ __forceinline__ void gemm_loop(const float* __restrict__ Ablk,
                                          const float* __restrict__ Bblk,
                                          int K, uint32_t* sA, uint32_t* sB,
                                          float (&acc)[4][4][4])
{
    const int tid  = threadIdx.x;
    const int lane = tid & 31;
    const int wrp  = tid >> 5;
    const int wm   = (wrp & 1) * 64;
    const int wn   = (wrp >> 1) * 32;

    const int krow = tid >> 3;
    const int kcol = (tid & 7) * 4;
    const int scol = (tid & 7) ^ (krow & 7);
    const float* Ag = Ablk + (size_t)krow * K + kcol;
    const float* Bg = Bblk + (size_t)krow * K + kcol;

    const int a_m   = wm + (lane & 15);
    const int a_k4b = lane >> 4;
    const int b_n   = wn + (lane & 7) + ((lane & 16) >> 1);
    const int b_k4b = (lane >> 3) & 1;
    const int l7    = lane & 7;

    const int nkt = K >> 5;

    float4 ra[2][4], rb[2][4];
#pragma unroll
    for (int st = 0; st < 2; st++) {
        if (st < nkt) {
            const float* An = Ag + st * 32;
            const float* Bn = Bg + st * 32;
#pragma unroll
            for (int p = 0; p < 4; p++) {
                ra[st][p] = *(const float4*)(An + (size_t)(32 * p) * K);
                rb[st][p] = *(const float4*)(Bn + (size_t)(32 * p) * K);
            }
        }
    }

    for (int kt = 0; kt < nkt; kt++) {
        const int st = kt & 1;
        uint32_t* dA = sA + st * 4096;
        uint32_t* dB = sB + st * 4096;
        __syncthreads();   // readers of buffer st (iter kt-2) are done
#pragma unroll
        for (int p = 0; p < 4; p++) {
            int m = krow + 32 * p;
            uint4 va = make_uint4(f2tf(ra[st][p].x), f2tf(ra[st][p].y),
                                  f2tf(ra[st][p].z), f2tf(ra[st][p].w));
            uint4 vb = make_uint4(f2tf(rb[st][p].x), f2tf(rb[st][p].y),
                                  f2tf(rb[st][p].z), f2tf(rb[st][p].w));
            *(uint4*)(dA + m * 32 + scol * 4) = va;
            *(uint4*)(dB + m * 32 + scol * 4) = vb;
        }
        __syncthreads();

        if (kt + 2 < nkt) {   // refill this stage for kt+2 (window = 2 iters)
            const float* An = Ag + (kt + 2) * 32;
            const float* Bn = Bg + (kt + 2) * 32;
#pragma unroll
            for (int p = 0; p < 4; p++) {
                ra[st][p] = *(const float4*)(An + (size_t)(32 * p) * K);
                rb[st][p] = *(const float4*)(Bn + (size_t)(32 * p) * K);
            }
        }

        const uint32_t baseA = (uint32_t)__cvta_generic_to_shared(dA);
        const uint32_t baseB = (uint32_t)__cvta_generic_to_shared(dB);

#pragma unroll
        for (int ks = 0; ks < 4; ks++) {
            uint32_t af[4][4];
#pragma unroll
            for (int mi = 0; mi < 4; mi++) {
                int m   = a_m + mi * 16;
                int col = (2 * ks + a_k4b) ^ l7;
                ldsm4(af[mi], baseA + (uint32_t)(m * 128 + col * 16));
            }
            uint32_t bf[2][4];
#pragma unroll
            for (int nj = 0; nj < 2; nj++) {
                int n   = b_n + nj * 16;
                int col = (2 * ks + b_k4b) ^ l7;
                ldsm4(bf[nj], baseB + (uint32_t)(n * 128 + col * 16));
            }
#pragma unroll
            for (int mi = 0; mi < 4; mi++) {
#pragma unroll
                for (int nj = 0; nj < 2; nj++) {
                    uint32_t b0[2] = {bf[nj][0], bf[nj][1]};
                    uint32_t b1[2] = {bf[nj][2], bf[nj][3]};
                    mma_tf32(acc[mi][nj * 2 + 0], af[mi], b0);
                    mma_tf32(acc[mi][nj * 2 + 1], af[mi], b1);
                }
            }
        }
    }
    __syncthreads();
}

__device__ __forceinline__ void store_tile(float* __restrict__ Cblk, int ldc,
                                           float (&acc)[4][4][4])
{
    const int tid  = threadIdx.x;
    const int lane = tid & 31;
    const int wrp  = tid >> 5;
    const int wm   = (wrp & 1) * 64;
    const int wn   = (wrp >> 1) * 32;
    const int crow = lane >> 2, ccol = (lane & 3) * 2;
#pragma unroll
    for (int mi = 0; mi < 4; mi++) {
#pragma unroll
        for (int ni = 0; ni < 4; ni++) {
            float* C0 = Cblk + (size_t)(wm + mi * 16 + crow) * ldc + wn + ni * 8 + ccol;
            *(float2*)C0 = make_float2(acc[mi][ni][0], acc[mi][ni][1]);
            *(float2*)(C0 + (size_t)8 * ldc) = make_float2(acc[mi][ni][2], acc[mi][ni][3]);
        }
    }
}

// ---------- fused input projections: Q | K | V | latent-in ----------
__global__ void __launch_bounds__(256) proj_kernel(const float* __restrict__ hidden,
                                                   const float* __restrict__ Wq,
                                                   const float* __restrict__ Wk,
                                                   const float* __restrict__ Wv,
                                                   const float* __restrict__ Wl,
                                                   float* __restrict__ q,
                                                   float* __restrict__ k,
                                                   float* __restrict__ v,
                                                   float* __restrict__ lat)
{
    extern __shared__ uint32_t shg[];
    uint32_t* sA = shg;
    uint32_t* sB = shg + 8192;

    const int bx = blockIdx.x;
    const int bm = blockIdx.y * 128;

    const float* W; float* C; int ldc, n0;
    if (bx < 16)      { W = Wq; C = q;   ldc = 2048; n0 = bx * 128; }
    else if (bx < 20) { W = Wk; C = k;   ldc = 512;  n0 = (bx - 16) * 128; }
    else if (bx < 24) { W = Wv; C = v;   ldc = 512;  n0 = (bx - 20) * 128; }
    else              { W = Wl; C = lat; ldc = 256;  n0 = (bx - 24) * 128; }

    float acc[4][4][4];
#pragma unroll
    for (int i = 0; i < 4; i++)
#pragma unroll
        for (int j = 0; j < 4; j++)
#pragma unroll
            for (int r = 0; r < 4; r++) acc[i][j][r] = 0.f;

    gemm_loop(hidden + (size_t)bm * H_, W + (size_t)n0 * H_, H_, sA, sB, acc);
    store_tile(C + (size_t)bm * ldc + n0, ldc, acc);
}

// ---------- fused output: out = ctx@Wo^T + gate * lat@Wl_out^T ----------
__global__ void __launch_bounds__(256) out_kernel(const float* __restrict__ ctx,
                                                  const float* __restrict__ lat,
                                                  const float* __restrict__ Wo,
                                                  const float* __restrict__ Wl_out,
                                                  const float* __restrict__ gate,
                                                  float* __restrict__ out)
{
    extern __shared__ uint32_t shg[];
    uint32_t* sA = shg;
    uint32_t* sB = shg + 8192;

    const int bm = blockIdx.y * 128;
    const int n0 = blockIdx.x * 128;

    float acc[4][4][4];
#pragma unroll
    for (int i = 0; i < 4; i++)
#pragma unroll
        for (int j = 0; j < 4; j++)
#pragma unroll
            for (int r = 0; r < 4; r++) acc[i][j][r] = 0.f;

    gemm_loop(lat + (size_t)bm * LAT_, Wl_out + (size_t)n0 * LAT_, LAT_, sA, sB, acc);
    const float g = *gate;
#pragma unroll
    for (int i = 0; i < 4; i++)
#pragma unroll
        for (int j = 0; j < 4; j++)
#pragma unroll
            for (int r = 0; r < 4; r++) acc[i][j][r] *= g;

    gemm_loop(ctx + (size_t)bm * H_, Wo + (size_t)n0 * H_, H_, sA, sB, acc);
    store_tile(out + (size_t)bm * H_ + n0, H_, acc);
}

// ---------------- RoPE (in place) ----------------
__global__ void rope_kernel(float* __restrict__ x, const float* __restrict__ cosT,
                            const float* __restrict__ sinT, int nheads)
{
    int idx = blockIdx.x * blockDim.x + threadIdx.x;
    int total = TOK * nheads * 64;
    if (idx >= total) return;
    int d = idx & 63;
    int h = (idx >> 6) % nheads;
    int t = idx / (64 * nheads);
    int s = t & (S_ - 1);
    float c  = cosT[s * HD_ + d];
    float sn = sinT[s * HD_ + d];
    float* p = x + (size_t)t * (nheads * HD_) + h * HD_ + d;
    float x1 = p[0], x2 = p[64];
    p[0]  = x1 * c - x2 * sn;
    p[64] = x2 * c + x1 * sn;
}

// ---------------- tf32 tensor-core causal flash attention (ldsm) --------
// BQ=128, BK=64, HD=128. 256 threads (8 warps), warp owns 16 Q rows.
#define ATT_SMEM_BYTES (24576 * 4)

__global__ void __launch_bounds__(256) attn_tc(const float* __restrict__ Q,
                                               const float* __restrict__ K,
                                               const float* __restrict__ V,
                                               float* __restrict__ O)
{
    extern __shared__ uint32_t smu[];
    uint32_t* Ks = smu;             // 8192
    uint32_t* Vt = smu + 8192;      // 8192
    uint32_t* Ps = smu + 16384;     // 8192

    const uint32_t baseK = (uint32_t)__cvta_generic_to_shared(Ks);
    const uint32_t baseV = (uint32_t)__cvta_generic_to_shared(Vt);
    const uint32_t baseP = (uint32_t)__cvta_generic_to_shared(Ps);

    // work-descending schedule: heaviest (largest qb) CTAs launch first
    const int qb = gridDim.x - 1 - blockIdx.x;
    const int h = blockIdx.y, b = blockIdx.z;
    const int kvh = h >> 2;
    const int tid = threadIdx.x, lane = tid & 31, w = tid >> 5;
    const int g = lane >> 2, t = lane & 3;
    const int m0 = w * 16;
    const int l7 = lane & 7;

    const float* Qh = Q + ((size_t)b * S_ + (size_t)qb * 128) * H_ + h * HD_;
    const float* Kh = K + (size_t)b * S_ * (NKV_ * HD_) + kvh * HD_;
    const float* Vh = V + (size_t)b * S_ * (NKV_ * HD_) + kvh * HD_;

    const float scale = 0.08838834764831845f;  // 1/sqrt(128)

    // Q fragments in registers, pre-scaled + tf32
    uint32_t qf[16][4];
    {
        const float* q0 = Qh + (size_t)(m0 + g) * H_;
        const float* q1 = Qh + (size_t)(m0 + g + 8) * H_;
#pragma unroll
        for (int kt = 0; kt < 16; kt++) {
            qf[kt][0] = f2tf(q0[kt * 8 + t] * scale);
            qf[kt][1] = f2tf(q1[kt * 8 + t] * scale);
            qf[kt][2] = f2tf(q0[kt * 8 + t + 4] * scale);
            qf[kt][3] = f2tf(q1[kt * 8 + t + 4] * scale);
        }
    }

    float accO[16][4];
#pragma unroll
    for (int dt = 0; dt < 16; dt++)
#pragma unroll
        for (int r = 0; r < 4; r++) accO[dt][r] = 0.f;

    const int row0 = qb * 128 + m0 + g;
    const int row1 = row0 + 8;
    float mr0 = -1e30f, mr1 = -1e30f, l0 = 0.f, l1 = 0.f;

    const int kbmax = 2 * qb + 1;
    const int warp_min_row = qb * 128 + m0;

    const int k_rbase = tid >> 3;
    const int k_j     = tid & 7;
    const int v_c     = w * 8 + (tid & 7);
    const int v_cs    = (tid >> 3) & 3;

    const int qk_bn   = (lane & 7) + ((lane & 16) >> 1);
    const int qk_k4b  = (lane >> 3) & 1;
    const int pa_m    = m0 + (lane & 15);
    const int pa_k4b  = lane >> 4;

    for (int kb = 0; kb <= kbmax; kb++) {
        __syncthreads();
        // ---- load K tile into swizzled ldsm layout ----
        {
            const float* kbp = Kh + (size_t)(kb * 64) * (NKV_ * HD_);
#pragma unroll
            for (int p = 0; p < 2; p++) {
                int n = k_rbase + 32 * p;
                const float* src = kbp + (size_t)n * (NKV_ * HD_);
#pragma unroll
                for (int f = 0; f < 4; f++) {
                    int c4 = k_j + 8 * f;
                    float4 kv = *(const float4*)(src + c4 * 4);
                    uint4 va = make_uint4(f2tf(kv.x), f2tf(kv.y), f2tf(kv.z), f2tf(kv.w));
                    *(uint4*)(Ks + n * 128 + ((c4 ^ (n & 7)) * 4)) = va;
                }
            }
        }
        // ---- load V tile transposed into swizzled ldsm layout ----
        {
            const float* vbp = Vh + (size_t)(kb * 64 + v_c) * (NKV_ * HD_);
            const int c4v = v_c >> 2, c3v = v_c & 3;
#pragma unroll
            for (int f = 0; f < 8; f++) {
                int chunk = v_cs + 4 * f;
                float4 vv = *(const float4*)(vbp + chunk * 4);
                int d0 = chunk * 4;
                Vt[(d0 + 0) * 64 + ((c4v ^ ((d0 + 0) & 7)) * 4) + c3v] = f2tf(vv.x);
                Vt[(d0 + 1) * 64 + ((c4v ^ ((d0 + 1) & 7)) * 4) + c3v] = f2tf(vv.y);
                Vt[(d0 + 2) * 64 + ((c4v ^ ((d0 + 2) & 7)) * 4) + c3v] = f2tf(vv.z);
                Vt[(d0 + 3) * 64 + ((c4v ^ ((d0 + 3) & 7)) * 4) + c3v] = f2tf(vv.w);
            }
        }
        __syncthreads();

        // ---- S = (Q*scale) @ K^T ----
        float s[8][4];
#pragma unroll
        for (int nt = 0; nt < 8; nt++) {
            s[nt][0] = 0.f; s[nt][1] = 0.f; s[nt][2] = 0.f; s[nt][3] = 0.f;
        }
#pragma unroll
        for (int ks = 0; ks < 16; ks++) {
            int col = (2 * ks + qk_k4b) & 31;
            col = col ^ l7;
#pragma unroll
            for (int nt2 = 0; nt2 < 4; nt2++) {
                uint32_t bf[4];
                int n = qk_bn + nt2 * 16;
                ldsm4(bf, baseK + (uint32_t)(n * 512 + col * 16));
                uint32_t b0[2] = {bf[0], bf[1]};
                uint32_t b1[2] = {bf[2], bf[3]};
                mma_tf32(s[nt2 * 2 + 0], qf[ks], b0);
                mma_tf32(s[nt2 * 2 + 1], qf[ks], b1);
            }
        }

        const int cbase = kb * 64;
        if (cbase + 63 > warp_min_row) {
#pragma unroll
            for (int nt = 0; nt < 8; nt++) {
                int c0 = cbase + nt * 8 + 2 * t;
                int c1 = c0 + 1;
                if (c0 > row0) s[nt][0] = -1e30f;
                if (c1 > row0) s[nt][1] = -1e30f;
                if (c0 > row1) s[nt][2] = -1e30f;
                if (c1 > row1) s[nt][3] = -1e30f;
            }
        }

        // ---- online softmax ----
        float mb0 = -1e30f, mb1 = -1e30f;
#pragma unroll
        for (int nt = 0; nt < 8; nt++) {
            mb0 = fmaxf(mb0, fmaxf(s[nt][0], s[nt][1]));
            mb1 = fmaxf(mb1, fmaxf(s[nt][2], s[nt][3]));
        }
        mb0 = fmaxf(mb0, __shfl_xor_sync(0xffffffffu, mb0, 1));
        mb0 = fmaxf(mb0, __shfl_xor_sync(0xffffffffu, mb0, 2));
        mb1 = fmaxf(mb1, __shfl_xor_sync(0xffffffffu, mb1, 1));
        mb1 = fmaxf(mb1, __shfl_xor_sync(0xffffffffu, mb1, 2));

        float mn0 = fmaxf(mr0, mb0), mn1 = fmaxf(mr1, mb1);
        float corr0 = __expf(mr0 - mn0), corr1 = __expf(mr1 - mn1);
        mr0 = mn0; mr1 = mn1;

        float ps0 = 0.f, ps1 = 0.f;
        {
            const int inner = (t & 1) * 2;
#pragma unroll
            for (int nt = 0; nt < 8; nt++) {
                float p0 = __expf(s[nt][0] - mn0);
                float p1 = __expf(s[nt][1] - mn0);
                float p2 = __expf(s[nt][2] - mn1);
                float p3 = __expf(s[nt][3] - mn1);
                ps0 += p0 + p1;
                ps1 += p2 + p3;
                int c4b = 2 * nt + (t >> 1);
                int sc  = (c4b ^ g) * 4 + inner;
                *(uint2*)(Ps + (m0 + g) * 64 + sc)     = make_uint2(f2tf(p0), f2tf(p1));
                *(uint2*)(Ps + (m0 + g + 8) * 64 + sc) = make_uint2(f2tf(p2), f2tf(p3));
            }
        }
        ps0 += __shfl_xor_sync(0xffffffffu, ps0, 1);
        ps0 += __shfl_xor_sync(0xffffffffu, ps0, 2);
        ps1 += __shfl_xor_sync(0xffffffffu, ps1, 1);
        ps1 += __shfl_xor_sync(0xffffffffu, ps1, 2);
        l0 = l0 * corr0 + ps0;
        l1 = l1 * corr1 + ps1;

#pragma unroll
        for (int dt = 0; dt < 16; dt++) {
            accO[dt][0] *= corr0; accO[dt][1] *= corr0;
            accO[dt][2] *= corr1; accO[dt][3] *= corr1;
        }

        __syncwarp();

        // ---- PV via ldsm A-frags (P) and B-frags (Vt) ----
#pragma unroll
        for (int ct = 0; ct < 8; ct++) {
            uint32_t pa[4];
            {
                int col = (2 * ct + pa_k4b) ^ l7;
                ldsm4(pa, baseP + (uint32_t)(pa_m * 256 + col * 16));
            }
            int bcol = (2 * ct + qk_k4b) ^ l7;
#pragma unroll
            for (int dt2 = 0; dt2 < 8; dt2++) {
                uint32_t vb[4];
                int d = qk_bn + dt2 * 16;
                ldsm4(vb, baseV + (uint32_t)(d * 256 + bcol * 16));
                uint32_t b0[2] = {vb[0], vb[1]};
                uint32_t b1[2] = {vb[2], vb[3]};
                mma_tf32(accO[dt2 * 2 + 0], pa, b0);
                mma_tf32(accO[dt2 * 2 + 1], pa, b1);
            }
        }
    }

    // ---- epilogue ----
    float inv0 = 1.f / l0, inv1 = 1.f / l1;
    float* O0 = O + ((size_t)b * S_ + row0) * H_ + h * HD_;
    float* O1 = O + ((size_t)b * S_ + row1) * H_ + h * HD_;
#pragma unroll
    for (int dt = 0; dt < 16; dt++) {
        int c = dt * 8 + 2 * t;
        *(float2*)(O0 + c) = make_float2(accO[dt][0] * inv0, accO[dt][1] * inv0);
        *(float2*)(O1 + c) = make_float2(accO[dt][2] * inv1, accO[dt][3] * inv1);
    }
}

// ---------------- host ----------------
extern "C" void kernel_launch(void* const* d_in, const int* in_sizes, int n_in,
                              void* d_out, int out_size)
{
    const float* hidden = (const float*)d_in[0];
    const float* cosT   = (const float*)d_in[1];
    const float* sinT   = (const float*)d_in[2];
    const float* Wq     = (const float*)d_in[4];
    const float* Wk     = (const float*)d_in[5];
    const float* Wv     = (const float*)d_in[6];
    const float* Wo     = (const float*)d_in[7];
    const float* Wl_in  = (const float*)d_in[8];
    const float* Wl_out = (const float*)d_in[9];
    const float* gate   = (const float*)d_in[10];
    float* out = (float*)d_out;

    float *q, *k, *v, *lat, *ctx;
    cudaGetSymbolAddress((void**)&q,   gQ);
    cudaGetSymbolAddress((void**)&k,   gK);
    cudaGetSymbolAddress((void**)&v,   gV);
    cudaGetSymbolAddress((void**)&lat, gLat);
    cudaGetSymbolAddress((void**)&ctx, gCtx);

    const int gemm_smem = 16384 * (int)sizeof(uint32_t);  // 64 KB
    cudaFuncSetAttribute(proj_kernel, cudaFuncAttributeMaxDynamicSharedMemorySize, gemm_smem);
    cudaFuncSetAttribute(out_kernel,  cudaFuncAttributeMaxDynamicSharedMemorySize, gemm_smem);
    cudaFuncSetAttribute(attn_tc, cudaFuncAttributeMaxDynamicSharedMemorySize, ATT_SMEM_BYTES);

    // fused projections: Q | K | V | latent-in
    proj_kernel<<<dim3(26, TOK / 128), 256, gemm_smem>>>(hidden, Wq, Wk, Wv, Wl_in,
                                                         q, k, v, lat);

    // RoPE
    {
        int nq = TOK * NH_ * 64;
        rope_kernel<<<(nq + 255) / 256, 256>>>(q, cosT, sinT, NH_);
        int nk = TOK * NKV_ * 64;
        rope_kernel<<<(nk + 255) / 256, 256>>>(k, cosT, sinT, NKV_);
    }

    // attention (tf32 tensor cores, ldmatrix everywhere)
    attn_tc<<<dim3(S_ / 128, NH_, B_), 256, ATT_SMEM_BYTES>>>(q, k, v, ctx);

    // fused output: Wo projection + gated latent branch
    out_kernel<<<dim3(H_ / 128, TOK / 128), 256, gemm_smem>>>(ctx, lat, Wo, Wl_out,
                                                              gate, out);
}

// round 16
// speedup vs baseline: 1.1405x; 1.1405x over previous
#include <cuda_runtime.h>
#include <math.h>
#include <stdint.h>

#define B_   2
#define S_   2048
#define H_   2048
#define NH_  16
#define NKV_ 4
#define HD_  128
#define LAT_ 256
#define TOK  (B_ * S_)

// ---------------- scratch (no allocations allowed) ----------------
__device__ float gQ[(size_t)TOK * H_];            // 32 MB
__device__ float gK[(size_t)TOK * NKV_ * HD_];    // 8 MB
__device__ float gV[(size_t)TOK * NKV_ * HD_];    // 8 MB
__device__ float gLat[(size_t)TOK * LAT_];        // 4 MB
__device__ float gCtx[(size_t)TOK * H_];          // 32 MB

// ---------------- tf32 helpers ----------------
__device__ __forceinline__ uint32_t f2tf(float x) {
    uint32_t r;
    asm("cvt.rna.tf32.f32 %0, %1;" : "=r"(r) : "f"(x));
    return r;
}

__device__ __forceinline__ void mma_tf32(float (&d)[4], const uint32_t (&a)[4],
                                         const uint32_t (&b)[2]) {
    asm volatile(
        "mma.sync.aligned.m16n8k8.row.col.f32.tf32.tf32.f32 "
        "{%0,%1,%2,%3}, {%4,%5,%6,%7}, {%8,%9}, {%0,%1,%2,%3};"
        : "+f"(d[0]), "+f"(d[1]), "+f"(d[2]), "+f"(d[3])
        : "r"(a[0]), "r"(a[1]), "r"(a[2]), "r"(a[3]), "r"(b[0]), "r"(b[1]));
}

__device__ __forceinline__ void ldsm4(uint32_t (&r)[4], uint32_t addr) {
    asm volatile("ldmatrix.sync.aligned.m8n8.x4.shared.b16 {%0,%1,%2,%3}, [%4];"
                 : "=r"(r[0]), "=r"(r[1]), "=r"(r[2]), "=r"(r[3]) : "r"(addr));
}

// =====================================================================
// GEMM core (R12 structure: single sync per ktile, prefetch distance 1)
// acc += Ablk[128,K] @ Bblk[128,K]^T   (NT, tf32 tensor cores)
// =====================================================================
__device__ __forceinline__ void gemm_loop(const float* __restrict__ Ablk,
                                          const float* __restrict__ Bblk,
                                          int K, uint32_t* sA, uint32_t* sB,
                                          float (&acc)[4][4][4])
{
    const int tid  = threadIdx.x;
    const int lane = tid & 31;
    const int wrp  = tid >> 5;
    const int wm   = (wrp & 1) * 64;
    const int wn   = (wrp >> 1) * 32;

    const int krow = tid >> 3;
    const int kcol = (tid & 7) * 4;
    const int scol = (tid & 7) ^ (krow & 7);
    const float* Ag = Ablk + (size_t)krow * K + kcol;
    const float* Bg = Bblk + (size_t)krow * K + kcol;

    const int a_m   = wm + (lane & 15);
    const int a_k4b = lane >> 4;
    const int b_n   = wn + (lane & 7) + ((lane & 16) >> 1);
    const int b_k4b = (lane >> 3) & 1;
    const int l7    = lane & 7;

    float4 ra[4], rb[4];
#pragma unroll
    for (int p = 0; p < 4; p++) {
        ra[p] = *(const float4*)(Ag + (size_t)(32 * p) * K);
        rb[p] = *(const float4*)(Bg + (size_t)(32 * p) * K);
    }

    const int nkt = K >> 5;
    for (int kt = 0; kt < nkt; kt++) {
        uint32_t* dA = sA + (kt & 1) * 4096;
        uint32_t* dB = sB + (kt & 1) * 4096;
#pragma unroll
        for (int p = 0; p < 4; p++) {
            int m = krow + 32 * p;
            uint4 va = make_uint4(f2tf(ra[p].x), f2tf(ra[p].y), f2tf(ra[p].z), f2tf(ra[p].w));
            uint4 vb = make_uint4(f2tf(rb[p].x), f2tf(rb[p].y), f2tf(rb[p].z), f2tf(rb[p].w));
            *(uint4*)(dA + m * 32 + scol * 4) = va;
            *(uint4*)(dB + m * 32 + scol * 4) = vb;
        }
        __syncthreads();

        if (kt + 1 < nkt) {
            const float* An = Ag + (kt + 1) * 32;
            const float* Bn = Bg + (kt + 1) * 32;
#pragma unroll
            for (int p = 0; p < 4; p++) {
                ra[p] = *(const float4*)(An + (size_t)(32 * p) * K);
                rb[p] = *(const float4*)(Bn + (size_t)(32 * p) * K);
            }
        }

        const uint32_t baseA = (uint32_t)__cvta_generic_to_shared(dA);
        const uint32_t baseB = (uint32_t)__cvta_generic_to_shared(dB);

#pragma unroll
        for (int ks = 0; ks < 4; ks++) {
            uint32_t af[4][4];
#pragma unroll
            for (int mi = 0; mi < 4; mi++) {
                int m   = a_m + mi * 16;
                int col = (2 * ks + a_k4b) ^ l7;
                ldsm4(af[mi], baseA + (uint32_t)(m * 128 + col * 16));
            }
            uint32_t bf[2][4];
#pragma unroll
            for (int nj = 0; nj < 2; nj++) {
                int n   = b_n + nj * 16;
                int col = (2 * ks + b_k4b) ^ l7;
                ldsm4(bf[nj], baseB + (uint32_t)(n * 128 + col * 16));
            }
#pragma unroll
            for (int mi = 0; mi < 4; mi++) {
#pragma unroll
                for (int nj = 0; nj < 2; nj++) {
                    uint32_t b0[2] = {bf[nj][0], bf[nj][1]};
                    uint32_t b1[2] = {bf[nj][2], bf[nj][3]};
                    mma_tf32(acc[mi][nj * 2 + 0], af[mi], b0);
                    mma_tf32(acc[mi][nj * 2 + 1], af[mi], b1);
                }
            }
        }
    }
    __syncthreads();
}

__device__ __forceinline__ void store_tile(float* __restrict__ Cblk, int ldc,
                                           float (&acc)[4][4][4])
{
    const int tid  = threadIdx.x;
    const int lane = tid & 31;
    const int wrp  = tid >> 5;
    const int wm   = (wrp & 1) * 64;
    const int wn   = (wrp >> 1) * 32;
    const int crow = lane >> 2, ccol = (lane & 3) * 2;
#pragma unroll
    for (int mi = 0; mi < 4; mi++) {
#pragma unroll
        for (int ni = 0; ni < 4; ni++) {
            float* C0 = Cblk + (size_t)(wm + mi * 16 + crow) * ldc + wn + ni * 8 + ccol;
            *(float2*)C0 = make_float2(acc[mi][ni][0], acc[mi][ni][1]);
            *(float2*)(C0 + (size_t)8 * ldc) = make_float2(acc[mi][ni][2], acc[mi][ni][3]);
        }
    }
}

// ---------- fused input projections: Q | K | V | latent-in ----------
__global__ void __launch_bounds__(256) proj_kernel(const float* __restrict__ hidden,
                                                   const float* __restrict__ Wq,
                                                   const float* __restrict__ Wk,
                                                   const float* __restrict__ Wv,
                                                   const float* __restrict__ Wl,
                                                   float* __restrict__ q,
                                                   float* __restrict__ k,
                                                   float* __restrict__ v,
                                                   float* __restrict__ lat)
{
    extern __shared__ uint32_t shg[];
    uint32_t* sA = shg;
    uint32_t* sB = shg + 8192;

    const int bx = blockIdx.x;
    const int bm = blockIdx.y * 128;

    const float* W; float* C; int ldc, n0;
    if (bx < 16)      { W = Wq; C = q;   ldc = 2048; n0 = bx * 128; }
    else if (bx < 20) { W = Wk; C = k;   ldc = 512;  n0 = (bx - 16) * 128; }
    else if (bx < 24) { W = Wv; C = v;   ldc = 512;  n0 = (bx - 20) * 128; }
    else              { W = Wl; C = lat; ldc = 256;  n0 = (bx - 24) * 128; }

    float acc[4][4][4];
#pragma unroll
    for (int i = 0; i < 4; i++)
#pragma unroll
        for (int j = 0; j < 4; j++)
#pragma unroll
            for (int r = 0; r < 4; r++) acc[i][j][r] = 0.f;

    gemm_loop(hidden + (size_t)bm * H_, W + (size_t)n0 * H_, H_, sA, sB, acc);
    store_tile(C + (size_t)bm * ldc + n0, ldc, acc);
}

// ---------- fused output: out = ctx@Wo^T + gate * lat@Wl_out^T ----------
__global__ void __launch_bounds__(256) out_kernel(const float* __restrict__ ctx,
                                                  const float* __restrict__ lat,
                                                  const float* __restrict__ Wo,
                                                  const float* __restrict__ Wl_out,
                                                  const float* __restrict__ gate,
                                                  float* __restrict__ out)
{
    extern __shared__ uint32_t shg[];
    uint32_t* sA = shg;
    uint32_t* sB = shg + 8192;

    const int bm = blockIdx.y * 128;
    const int n0 = blockIdx.x * 128;

    float acc[4][4][4];
#pragma unroll
    for (int i = 0; i < 4; i++)
#pragma unroll
        for (int j = 0; j < 4; j++)
#pragma unroll
            for (int r = 0; r < 4; r++) acc[i][j][r] = 0.f;

    gemm_loop(lat + (size_t)bm * LAT_, Wl_out + (size_t)n0 * LAT_, LAT_, sA, sB, acc);
    const float g = *gate;
#pragma unroll
    for (int i = 0; i < 4; i++)
#pragma unroll
        for (int j = 0; j < 4; j++)
#pragma unroll
            for (int r = 0; r < 4; r++) acc[i][j][r] *= g;

    gemm_loop(ctx + (size_t)bm * H_, Wo + (size_t)n0 * H_, H_, sA, sB, acc);
    store_tile(out + (size_t)bm * H_ + n0, H_, acc);
}

// ---------------- RoPE (in place) — used for K only ----------------
__global__ void rope_kernel(float* __restrict__ x, const float* __restrict__ cosT,
                            const float* __restrict__ sinT, int nheads)
{
    int idx = blockIdx.x * blockDim.x + threadIdx.x;
    int total = TOK * nheads * 64;
    if (idx >= total) return;
    int d = idx & 63;
    int h = (idx >> 6) % nheads;
    int t = idx / (64 * nheads);
    int s = t & (S_ - 1);
    float c  = cosT[s * HD_ + d];
    float sn = sinT[s * HD_ + d];
    float* p = x + (size_t)t * (nheads * HD_) + h * HD_ + d;
    float x1 = p[0], x2 = p[64];
    p[0]  = x1 * c - x2 * sn;
    p[64] = x2 * c + x1 * sn;
}

// ---------------- tf32 tensor-core causal flash attention (ldsm) --------
// BQ=128, BK=64, HD=128. 256 threads (8 warps), warp owns 16 Q rows.
// Q-RoPE fused into the prologue (reads raw Q projection).
#define ATT_SMEM_BYTES (24576 * 4)

__global__ void __launch_bounds__(256) attn_tc(const float* __restrict__ Q,
                                               const float* __restrict__ K,
                                               const float* __restrict__ V,
                                               const float* __restrict__ cosT,
                                               const float* __restrict__ sinT,
                                               float* __restrict__ O)
{
    extern __shared__ uint32_t smu[];
    uint32_t* Ks = smu;             // 8192
    uint32_t* Vt = smu + 8192;      // 8192
    uint32_t* Ps = smu + 16384;     // 8192

    const uint32_t baseK = (uint32_t)__cvta_generic_to_shared(Ks);
    const uint32_t baseV = (uint32_t)__cvta_generic_to_shared(Vt);
    const uint32_t baseP = (uint32_t)__cvta_generic_to_shared(Ps);

    // work-descending schedule: heaviest (largest qb) CTAs launch first
    const int qb = gridDim.x - 1 - blockIdx.x;
    const int h = blockIdx.y, b = blockIdx.z;
    const int kvh = h >> 2;
    const int tid = threadIdx.x, lane = tid & 31, w = tid >> 5;
    const int g = lane >> 2, t = lane & 3;
    const int m0 = w * 16;
    const int l7 = lane & 7;

    const float* Qh = Q + ((size_t)b * S_ + (size_t)qb * 128) * H_ + h * HD_;
    const float* Kh = K + (size_t)b * S_ * (NKV_ * HD_) + kvh * HD_;
    const float* Vh = V + (size_t)b * S_ * (NKV_ * HD_) + kvh * HD_;

    const float scale = 0.08838834764831845f;  // 1/sqrt(128)

    const int row0 = qb * 128 + m0 + g;   // sequence position of this thread's row pair
    const int row1 = row0 + 8;

    // Q fragments in registers: RoPE applied in-register, then scale + tf32.
    // pair structure: d = 8*kt + t (+4), partner d+64 lives at kt+8.
    uint32_t qf[16][4];
    {
        const float* q0 = Qh + (size_t)(m0 + g) * H_;
        const float* q1 = Qh + (size_t)(m0 + g + 8) * H_;
        const float* c0 = cosT + (size_t)row0 * HD_;
        const float* s0 = sinT + (size_t)row0 * HD_;
        const float* c1 = cosT + (size_t)row1 * HD_;
        const float* s1 = sinT + (size_t)row1 * HD_;
#pragma unroll
        for (int kt = 0; kt < 8; kt++) {
#pragma unroll
            for (int half = 0; half < 2; half++) {       // frag idx 0/2 (row0), 1/3 (row1)
                int d = kt * 8 + t + half * 4;           // d < 64
                // row0
                {
                    float a = q0[d], bb = q0[d + 64];
                    float c = c0[d], sn = s0[d];
                    qf[kt][half * 2]     = f2tf((a * c - bb * sn) * scale);
                    qf[kt + 8][half * 2] = f2tf((bb * c + a * sn) * scale);
                }
                // row1
                {
                    float a = q1[d], bb = q1[d + 64];
                    float c = c1[d], sn = s1[d];
                    qf[kt][half * 2 + 1]     = f2tf((a * c - bb * sn) * scale);
                    qf[kt + 8][half * 2 + 1] = f2tf((bb * c + a * sn) * scale);
                }
            }
        }
    }

    float accO[16][4];
#pragma unroll
    for (int dt = 0; dt < 16; dt++)
#pragma unroll
        for (int r = 0; r < 4; r++) accO[dt][r] = 0.f;

    float mr0 = -1e30f, mr1 = -1e30f, l0 = 0.f, l1 = 0.f;

    const int kbmax = 2 * qb + 1;
    const int warp_min_row = qb * 128 + m0;

    const int k_rbase = tid >> 3;
    const int k_j     = tid & 7;
    const int v_c     = w * 8 + (tid & 7);
    const int v_cs    = (tid >> 3) & 3;

    const int qk_bn   = (lane & 7) + ((lane & 16) >> 1);
    const int qk_k4b  = (lane >> 3) & 1;
    const int pa_m    = m0 + (lane & 15);
    const int pa_k4b  = lane >> 4;

    for (int kb = 0; kb <= kbmax; kb++) {
        __syncthreads();
        // ---- load K tile into swizzled ldsm layout ----
        {
            const float* kbp = Kh + (size_t)(kb * 64) * (NKV_ * HD_);
#pragma unroll
            for (int p = 0; p < 2; p++) {
                int n = k_rbase + 32 * p;
                const float* src = kbp + (size_t)n * (NKV_ * HD_);
#pragma unroll
                for (int f = 0; f < 4; f++) {
                    int c4 = k_j + 8 * f;
                    float4 kv = *(const float4*)(src + c4 * 4);
                    uint4 va = make_uint4(f2tf(kv.x), f2tf(kv.y), f2tf(kv.z), f2tf(kv.w));
                    *(uint4*)(Ks + n * 128 + ((c4 ^ (n & 7)) * 4)) = va;
                }
            }
        }
        // ---- load V tile transposed into swizzled ldsm layout ----
        {
            const float* vbp = Vh + (size_t)(kb * 64 + v_c) * (NKV_ * HD_);
            const int c4v = v_c >> 2, c3v = v_c & 3;
#pragma unroll
            for (int f = 0; f < 8; f++) {
                int chunk = v_cs + 4 * f;
                float4 vv = *(const float4*)(vbp + chunk * 4);
                int d0 = chunk * 4;
                Vt[(d0 + 0) * 64 + ((c4v ^ ((d0 + 0) & 7)) * 4) + c3v] = f2tf(vv.x);
                Vt[(d0 + 1) * 64 + ((c4v ^ ((d0 + 1) & 7)) * 4) + c3v] = f2tf(vv.y);
                Vt[(d0 + 2) * 64 + ((c4v ^ ((d0 + 2) & 7)) * 4) + c3v] = f2tf(vv.z);
                Vt[(d0 + 3) * 64 + ((c4v ^ ((d0 + 3) & 7)) * 4) + c3v] = f2tf(vv.w);
            }
        }
        __syncthreads();

        // ---- S = (Q*scale) @ K^T ----
        float s[8][4];
#pragma unroll
        for (int nt = 0; nt < 8; nt++) {
            s[nt][0] = 0.f; s[nt][1] = 0.f; s[nt][2] = 0.f; s[nt][3] = 0.f;
        }
#pragma unroll
        for (int ks = 0; ks < 16; ks++) {
            int col = (2 * ks + qk_k4b) & 31;
            col = col ^ l7;
#pragma unroll
            for (int nt2 = 0; nt2 < 4; nt2++) {
                uint32_t bf[4];
                int n = qk_bn + nt2 * 16;
                ldsm4(bf, baseK + (uint32_t)(n * 512 + col * 16));
                uint32_t b0[2] = {bf[0], bf[1]};
                uint32_t b1[2] = {bf[2], bf[3]};
                mma_tf32(s[nt2 * 2 + 0], qf[ks], b0);
                mma_tf32(s[nt2 * 2 + 1], qf[ks], b1);
            }
        }

        const int cbase = kb * 64;
        if (cbase + 63 > warp_min_row) {
#pragma unroll
            for (int nt = 0; nt < 8; nt++) {
                int c0 = cbase + nt * 8 + 2 * t;
                int c1 = c0 + 1;
                if (c0 > row0) s[nt][0] = -1e30f;
                if (c1 > row0) s[nt][1] = -1e30f;
                if (c0 > row1) s[nt][2] = -1e30f;
                if (c1 > row1) s[nt][3] = -1e30f;
            }
        }

        // ---- online softmax ----
        float mb0 = -1e30f, mb1 = -1e30f;
#pragma unroll
        for (int nt = 0; nt < 8; nt++) {
            mb0 = fmaxf(mb0, fmaxf(s[nt][0], s[nt][1]));
            mb1 = fmaxf(mb1, fmaxf(s[nt][2], s[nt][3]));
        }
        mb0 = fmaxf(mb0, __shfl_xor_sync(0xffffffffu, mb0, 1));
        mb0 = fmaxf(mb0, __shfl_xor_sync(0xffffffffu, mb0, 2));
        mb1 = fmaxf(mb1, __shfl_xor_sync(0xffffffffu, mb1, 1));
        mb1 = fmaxf(mb1, __shfl_xor_sync(0xffffffffu, mb1, 2));

        float mn0 = fmaxf(mr0, mb0), mn1 = fmaxf(mr1, mb1);
        float corr0 = __expf(mr0 - mn0), corr1 = __expf(mr1 - mn1);
        mr0 = mn0; mr1 = mn1;

        float ps0 = 0.f, ps1 = 0.f;
        {
            const int inner = (t & 1) * 2;
#pragma unroll
            for (int nt = 0; nt < 8; nt++) {
                float p0 = __expf(s[nt][0] - mn0);
                float p1 = __expf(s[nt][1] - mn0);
                float p2 = __expf(s[nt][2] - mn1);
                float p3 = __expf(s[nt][3] - mn1);
                ps0 += p0 + p1;
                ps1 += p2 + p3;
                int c4b = 2 * nt + (t >> 1);
                int sc  = (c4b ^ g) * 4 + inner;
                *(uint2*)(Ps + (m0 + g) * 64 + sc)     = make_uint2(f2tf(p0), f2tf(p1));
                *(uint2*)(Ps + (m0 + g + 8) * 64 + sc) = make_uint2(f2tf(p2), f2tf(p3));
            }
        }
        ps0 += __shfl_xor_sync(0xffffffffu, ps0, 1);
        ps0 += __shfl_xor_sync(0xffffffffu, ps0, 2);
        ps1 += __shfl_xor_sync(0xffffffffu, ps1, 1);
        ps1 += __shfl_xor_sync(0xffffffffu, ps1, 2);
        l0 = l0 * corr0 + ps0;
        l1 = l1 * corr1 + ps1;

#pragma unroll
        for (int dt = 0; dt < 16; dt++) {
            accO[dt][0] *= corr0; accO[dt][1] *= corr0;
            accO[dt][2] *= corr1; accO[dt][3] *= corr1;
        }

        __syncwarp();

        // ---- PV via ldsm A-frags (P) and B-frags (Vt) ----
#pragma unroll
        for (int ct = 0; ct < 8; ct++) {
            uint32_t pa[4];
            {
                int col = (2 * ct + pa_k4b) ^ l7;
                ldsm4(pa, baseP + (uint32_t)(pa_m * 256 + col * 16));
            }
            int bcol = (2 * ct + qk_k4b) ^ l7;
#pragma unroll
            for (int dt2 = 0; dt2 < 8; dt2++) {
                uint32_t vb[4];
                int d = qk_bn + dt2 * 16;
                ldsm4(vb, baseV + (uint32_t)(d * 256 + bcol * 16));
                uint32_t b0[2] = {vb[0], vb[1]};
                uint32_t b1[2] = {vb[2], vb[3]};
                mma_tf32(accO[dt2 * 2 + 0], pa, b0);
                mma_tf32(accO[dt2 * 2 + 1], pa, b1);
            }
        }
    }

    // ---- epilogue ----
    float inv0 = 1.f / l0, inv1 = 1.f / l1;
    float* O0 = O + ((size_t)b * S_ + row0) * H_ + h * HD_;
    float* O1 = O + ((size_t)b * S_ + row1) * H_ + h * HD_;
#pragma unroll
    for (int dt = 0; dt < 16; dt++) {
        int c = dt * 8 + 2 * t;
        *(float2*)(O0 + c) = make_float2(accO[dt][0] * inv0, accO[dt][1] * inv0);
        *(float2*)(O1 + c) = make_float2(accO[dt][2] * inv1, accO[dt][3] * inv1);
    }
}

// ---------------- host ----------------
extern "C" void kernel_launch(void* const* d_in, const int* in_sizes, int n_in,
                              void* d_out, int out_size)
{
    const float* hidden = (const float*)d_in[0];
    const float* cosT   = (const float*)d_in[1];
    const float* sinT   = (const float*)d_in[2];
    const float* Wq     = (const float*)d_in[4];
    const float* Wk     = (const float*)d_in[5];
    const float* Wv     = (const float*)d_in[6];
    const float* Wo     = (const float*)d_in[7];
    const float* Wl_in  = (const float*)d_in[8];
    const float* Wl_out = (const float*)d_in[9];
    const float* gate   = (const float*)d_in[10];
    float* out = (float*)d_out;

    float *q, *k, *v, *lat, *ctx;
    cudaGetSymbolAddress((void**)&q,   gQ);
    cudaGetSymbolAddress((void**)&k,   gK);
    cudaGetSymbolAddress((void**)&v,   gV);
    cudaGetSymbolAddress((void**)&lat, gLat);
    cudaGetSymbolAddress((void**)&ctx, gCtx);

    const int gemm_smem = 16384 * (int)sizeof(uint32_t);  // 64 KB
    cudaFuncSetAttribute(proj_kernel, cudaFuncAttributeMaxDynamicSharedMemorySize, gemm_smem);
    cudaFuncSetAttribute(out_kernel,  cudaFuncAttributeMaxDynamicSharedMemorySize, gemm_smem);
    cudaFuncSetAttribute(attn_tc, cudaFuncAttributeMaxDynamicSharedMemorySize, ATT_SMEM_BYTES);

    // fused projections: Q | K | V | latent-in
    proj_kernel<<<dim3(26, TOK / 128), 256, gemm_smem>>>(hidden, Wq, Wk, Wv, Wl_in,
                                                         q, k, v, lat);

    // RoPE on K only (Q-RoPE is fused into attn_tc prologue)
    {
        int nk = TOK * NKV_ * 64;
        rope_kernel<<<(nk + 255) / 256, 256>>>(k, cosT, sinT, NKV_);
    }

    // attention (tf32 tensor cores, ldmatrix everywhere, fused Q-RoPE)
    attn_tc<<<dim3(S_ / 128, NH_, B_), 256, ATT_SMEM_BYTES>>>(q, k, v, cosT, sinT, ctx);

    // fused output: Wo projection + gated latent branch
    out_kernel<<<dim3(H_ / 128, TOK / 128), 256, gemm_smem>>>(ctx, lat, Wo, Wl_out,
                                                              gate, out);
}